// round 6
// baseline (speedup 1.0000x reference)
#include <cuda_runtime.h>
#include <cstdint>

#define HDIM 1024
#define NCTA 128
#define NTHR 512

// Persistent cross-kernel state (allocation-free: __device__ globals).
__device__ unsigned g_flags[NCTA];      // per-CTA progress flags (step index published)
__device__ float g_hbuf[2][HDIM];       // double-buffered hidden state

__global__ void lstm_init_kernel() { g_flags[threadIdx.x] = 0u; }

__device__ __forceinline__ unsigned ld_acquire_gpu(const unsigned* p) {
    unsigned v;
    asm volatile("ld.acquire.gpu.global.u32 %0, [%1];" : "=r"(v) : "l"(p) : "memory");
    return v;
}
__device__ __forceinline__ void st_flag_release(unsigned* p, unsigned v) {
    // CTA-wide writes ordered via preceding __syncwarp/__syncthreads; this
    // fence + relaxed store publishes them at gpu scope (pairs with ld.acquire).
    asm volatile("fence.acq_rel.gpu;" ::: "memory");
    asm volatile("st.global.relaxed.gpu.u32 [%0], %1;" :: "l"(p), "r"(v) : "memory");
}
__device__ __forceinline__ float2 ldcg_f2(const float2* p) {
    float2 v;
    asm volatile("ld.global.cg.v2.f32 {%0,%1}, [%2];" : "=f"(v.x), "=f"(v.y) : "l"(p) : "memory");
    return v;
}
// Packed fp32x2 FMA (Blackwell): d.lo = fma(a.lo,b.lo,d.lo), d.hi = fma(a.hi,b.hi,d.hi)
__device__ __forceinline__ void fma2(unsigned long long& d, unsigned long long a, unsigned long long b) {
    asm volatile("fma.rn.f32x2 %0, %1, %2, %0;" : "+l"(d) : "l"(a), "l"(b));
}
__device__ __forceinline__ float2 unpack2(unsigned long long v) {
    float2 r;
    asm("mov.b64 {%0, %1}, %2;" : "=f"(r.x), "=f"(r.y) : "l"(v));
    return r;
}

// 128 CTAs x 512 threads. CTA b owns hidden indices [8b, 8b+8).
// Warp w (0..15) owns gate rows r0=2w, r1=2w+1 (r = gate*8 + jj), global row
// R = (r>>3)*1024 + 8b + (r&7). Each lane holds 64 W_hh weights as 32 packed
// fp32x2 pairs in registers (2 rows x 32 cols, k = c*128 + lane*4 + d).
__global__ void __launch_bounds__(NTHR, 1)
lstm_kernel(const float* __restrict__ x,
            const float* __restrict__ W_ih,
            const float* __restrict__ W_hh,
            const float* __restrict__ b_ih,
            const float* __restrict__ b_hh,
            const int*   __restrict__ nn,
            float*       __restrict__ out)
{
    __shared__ float hsm[HDIM];
    __shared__ float gsm[32];

    const int tid = threadIdx.x;
    const int w   = tid >> 5;
    const int l   = tid & 31;
    const int b   = blockIdx.x;
    const int N   = *nn;

    const int r0 = 2 * w;
    const int r1 = 2 * w + 1;
    const int R0 = (r0 >> 3) * HDIM + b * 8 + (r0 & 7);
    const int R1 = (r1 >> 3) * HDIM + b * 8 + (r1 & 7);
    const int kb = l * 4;

    // Stage x into hsm (only needed for the x-gates precompute).
    {
        float2 v = *(const float2*)(x + 2 * tid);
        *(float2*)(hsm + 2 * tid) = v;
    }

    // Pin W_hh weights in registers as packed fp32x2 pairs (coalesced 16B loads).
    ulonglong2 wA2[8], wB2[8];
    {
        const ulonglong2* pA = (const ulonglong2*)(W_hh + (size_t)R0 * HDIM + kb);
        const ulonglong2* pB = (const ulonglong2*)(W_hh + (size_t)R1 * HDIM + kb);
        #pragma unroll
        for (int c = 0; c < 8; c++) {
            wA2[c] = __ldg(pA + c * 32);   // +c*128 floats = +32 ulonglong2
            wB2[c] = __ldg(pB + c * 32);
        }
    }
    __syncthreads();   // x staged in hsm

    // x_gates = x @ W_ih^T + b_ih + b_hh for rows R0, R1 (stream W_ih once).
    float xgA, xgB;
    {
        float aA = 0.f, aB = 0.f;
        const float4* pA = (const float4*)(W_ih + (size_t)R0 * HDIM + kb);
        const float4* pB = (const float4*)(W_ih + (size_t)R1 * HDIM + kb);
        #pragma unroll
        for (int c = 0; c < 8; c++) {
            float4 hv = *(const float4*)(hsm + c * 128 + kb);
            float4 a  = __ldg(pA + c * 32);
            float4 q  = __ldg(pB + c * 32);
            aA = fmaf(a.x, hv.x, fmaf(a.y, hv.y, fmaf(a.z, hv.z, fmaf(a.w, hv.w, aA))));
            aB = fmaf(q.x, hv.x, fmaf(q.y, hv.y, fmaf(q.z, hv.z, fmaf(q.w, hv.w, aB))));
        }
        #pragma unroll
        for (int off = 16; off; off >>= 1) {
            aA += __shfl_xor_sync(0xffffffffu, aA, off);
            aB += __shfl_xor_sync(0xffffffffu, aB, off);
        }
        xgA = aA + b_ih[R0] + b_hh[R0];
        xgB = aB + b_ih[R1] + b_hh[R1];
    }

    float cstate = 0.f;   // cell state: lives in warp 0 lanes 0..7

    // ---- step 0: h = 0 -> gates = x_gates ----
    if (l == 0) { gsm[r0] = xgA; gsm[r1] = xgB; }
    __syncthreads();
    if (w == 0) {
        // Warp-wide gate evaluation: lane l handles gate row l.
        float xv = gsm[l];
        const bool isG = (l >= 16) && (l < 24);           // tanh rows
        float e = __expf(isG ? -2.0f * xv : -xv);
        float r = __fdividef(1.0f, 1.0f + e);
        float v = isG ? fmaf(2.0f, r, -1.0f) : r;
        float fg = __shfl_sync(0xffffffffu, v, (l + 8)  & 31);
        float gg = __shfl_sync(0xffffffffu, v, (l + 16) & 31);
        float og = __shfl_sync(0xffffffffu, v, (l + 24) & 31);
        if (l < 8) {
            float c = fmaf(fg, cstate, v * gg);
            cstate  = c;
            float e2 = __expf(-2.0f * c);
            float h  = og * fmaf(2.0f, __fdividef(1.0f, 1.0f + e2), -1.0f);
            int col  = b * 8 + l;
            g_hbuf[1][col] = h;           // h_1 -> buf[1]
            out[col] = h;                 // out row 0 = h_1
        }
        __syncwarp();
        if (l == 0) st_flag_release(&g_flags[b], 1u);
    }

    // ---- steps 1..N-1 ----
    for (int s = 1; s < N; s++) {
        // Every warp independently waits until all 128 CTAs published h_s.
        {
            const unsigned tgt = (unsigned)s;
            for (;;) {
                unsigned f0 = ld_acquire_gpu(&g_flags[l]);
                unsigned f1 = ld_acquire_gpu(&g_flags[l + 32]);
                unsigned f2 = ld_acquire_gpu(&g_flags[l + 64]);
                unsigned f3 = ld_acquire_gpu(&g_flags[l + 96]);
                bool ok = (f0 >= tgt) & (f1 >= tgt) & (f2 >= tgt) & (f3 >= tgt);
                if (__all_sync(0xffffffffu, ok)) break;
            }
        }
        // This warp stages its 64-float slice of h_s into shared (L2-fresh via .cg).
        {
            float2 hv = ldcg_f2((const float2*)&g_hbuf[s & 1][0] + (w * 32 + l));
            *(float2*)(hsm + w * 64 + l * 2) = hv;
        }
        __syncthreads();   // (A) hsm ready; also fences gsm reuse

        // Matvec with packed fp32x2 FMA: 2 rows per warp, 32 packed FMA/thread.
        unsigned long long aA0 = 0ull, aA1 = 0ull, aB0 = 0ull, aB1 = 0ull;
        #pragma unroll
        for (int c = 0; c < 8; c++) {
            ulonglong2 hv = *(const ulonglong2*)(hsm + c * 128 + kb);
            fma2(aA0, wA2[c].x, hv.x);
            fma2(aA1, wA2[c].y, hv.y);
            fma2(aB0, wB2[c].x, hv.x);
            fma2(aB1, wB2[c].y, hv.y);
        }
        float2 uA0 = unpack2(aA0), uA1 = unpack2(aA1);
        float2 uB0 = unpack2(aB0), uB1 = unpack2(aB1);
        float aA = (uA0.x + uA0.y) + (uA1.x + uA1.y);
        float aB = (uB0.x + uB0.y) + (uB1.x + uB1.y);
        #pragma unroll
        for (int off = 16; off; off >>= 1) {
            aA += __shfl_xor_sync(0xffffffffu, aA, off);
            aB += __shfl_xor_sync(0xffffffffu, aB, off);
        }
        if (l == 0) { gsm[r0] = aA + xgA; gsm[r1] = aB + xgB; }
        __syncthreads();   // (B) gsm ready

        // Warp 0: gate nonlinearities + state update for this CTA's 8 units.
        if (w == 0) {
            float xv = gsm[l];
            const bool isG = (l >= 16) && (l < 24);
            float e = __expf(isG ? -2.0f * xv : -xv);
            float r = __fdividef(1.0f, 1.0f + e);
            float v = isG ? fmaf(2.0f, r, -1.0f) : r;
            float fg = __shfl_sync(0xffffffffu, v, (l + 8)  & 31);
            float gg = __shfl_sync(0xffffffffu, v, (l + 16) & 31);
            float og = __shfl_sync(0xffffffffu, v, (l + 24) & 31);
            if (l < 8) {
                float c = fmaf(fg, cstate, v * gg);
                cstate  = c;
                float e2 = __expf(-2.0f * c);
                float h  = og * fmaf(2.0f, __fdividef(1.0f, 1.0f + e2), -1.0f);
                int col  = b * 8 + l;
                g_hbuf[(s + 1) & 1][col] = h;
                out[(size_t)s * HDIM + col] = h;   // out row s = h_{s+1}
            }
            __syncwarp();
            if (l == 0) st_flag_release(&g_flags[b], (unsigned)(s + 1));
        }
        // No trailing barrier needed: warps 1..15 proceed to poll flags >= s+1,
        // which only succeed after this CTA's warp 0 publishes; barrier (A) of
        // step s+1 orders all hsm/gsm reuse behind warp 0's reads.
    }
}

extern "C" void kernel_launch(void* const* d_in, const int* in_sizes, int n_in,
                              void* d_out, int out_size) {
    const float* x    = (const float*)d_in[0];   // projected_representation [1,1024]
    const float* Wih  = (const float*)d_in[1];   // [4096,1024]
    const float* Whh  = (const float*)d_in[2];   // [4096,1024]
    const float* bih  = (const float*)d_in[3];   // [4096]
    const float* bhh  = (const float*)d_in[4];   // [4096]
    const int*   nn   = (const int*)d_in[5];     // num_nodes
    float* out = (float*)d_out;                  // [N,1024] fp32

    lstm_init_kernel<<<1, NCTA>>>();
    lstm_kernel<<<NCTA, NTHR>>>(x, Wih, Whh, bih, bhh, nn, out);
}

// round 7
// speedup vs baseline: 2.6209x; 2.6209x over previous
#include <cuda_runtime.h>
#include <cstdint>

#define HDIM 1024
#define NCTA 128
#define NTHR 512

// Persistent cross-kernel state (allocation-free: __device__ globals).
__device__ unsigned g_flags[NCTA];      // per-CTA progress flags (published step index)
__device__ float g_hbuf[2][HDIM];       // double-buffered hidden state

__global__ void lstm_init_kernel() { g_flags[threadIdx.x] = 0u; }

__device__ __forceinline__ unsigned ld_acquire_gpu(const unsigned* p) {
    unsigned v;
    asm volatile("ld.acquire.gpu.global.u32 %0, [%1];" : "=r"(v) : "l"(p) : "memory");
    return v;
}
__device__ __forceinline__ void st_flag_release(unsigned* p, unsigned v) {
    asm volatile("fence.acq_rel.gpu;" ::: "memory");
    asm volatile("st.global.relaxed.gpu.u32 [%0], %1;" :: "l"(p), "r"(v) : "memory");
}
__device__ __forceinline__ float2 ldcg_f2(const float2* p) {
    float2 v;
    asm volatile("ld.global.cg.v2.f32 {%0,%1}, [%2];" : "=f"(v.x), "=f"(v.y) : "l"(p) : "memory");
    return v;
}
// Packed fp32x2 FMA (Blackwell): d.lo += a.lo*b.lo, d.hi += a.hi*b.hi (full fp32)
__device__ __forceinline__ void fma2(unsigned long long& d, unsigned long long a, unsigned long long b) {
    asm volatile("fma.rn.f32x2 %0, %1, %2, %0;" : "+l"(d) : "l"(a), "l"(b));
}
__device__ __forceinline__ float2 unpack2(unsigned long long v) {
    float2 r;
    asm("mov.b64 {%0, %1}, %2;" : "=f"(r.x), "=f"(r.y) : "l"(v));
    return r;
}

// 128 CTAs x 512 threads. CTA b owns hidden units [8b, 8b+8) => 32 gate rows
// (local row r = gate*8 + jj, global row R = (r>>3)*1024 + b*8 + (r&7)).
// Warp pair p = w>>1 owns local rows {4p..4p+3}; ch = w&1 selects the column
// half [512*ch, 512*ch+512). Each lane holds 4 rows x 16 cols of W_hh in
// registers (16 packed-f32x2 ulonglong2 = 64 floats). Partial row sums are
// combined across the warp pair through psum[] in shared memory.
__global__ void __launch_bounds__(NTHR, 1)
lstm_kernel(const float* __restrict__ x,
            const float* __restrict__ W_ih,
            const float* __restrict__ W_hh,
            const float* __restrict__ b_ih,
            const float* __restrict__ b_hh,
            const int*   __restrict__ nn,
            float*       __restrict__ out)
{
    __shared__ float hsm[HDIM];
    __shared__ float psum[64];     // [warp*4 + rowslot]

    const int tid = threadIdx.x;
    const int w   = tid >> 5;
    const int l   = tid & 31;
    const int b   = blockIdx.x;
    const int N   = *nn;

    const int p   = w >> 1;
    const int ch  = w & 1;
    const int kb  = ch * 512 + l * 4;      // base column for this lane

    int R[4];
    #pragma unroll
    for (int j = 0; j < 4; j++) {
        int r = 4 * p + j;
        R[j] = (r >> 3) * HDIM + b * 8 + (r & 7);
    }

    // Stage x into hsm (reused for h each step).
    *(float2*)(hsm + 2 * tid) = *(const float2*)(x + 2 * tid);

    // Pin W_hh weights in registers: wt[j][c] covers row R[j], cols kb+c*128..+3.
    ulonglong2 wt[4][4];
    #pragma unroll
    for (int j = 0; j < 4; j++) {
        const char* base = (const char*)(W_hh + (size_t)R[j] * HDIM + kb);
        #pragma unroll
        for (int c = 0; c < 4; c++)
            wt[j][c] = __ldg((const ulonglong2*)(base + c * 512));
    }
    __syncthreads();   // x staged

    // x-gate partials over this warp's column half (+ biases on even warp only).
    float xg[4];
    {
        unsigned long long a0[4] = {0,0,0,0}, a1[4] = {0,0,0,0};
        #pragma unroll
        for (int c = 0; c < 4; c++) {
            ulonglong2 hv = *(const ulonglong2*)(hsm + kb + c * 128);
            #pragma unroll
            for (int j = 0; j < 4; j++) {
                ulonglong2 wv = __ldg((const ulonglong2*)
                    ((const char*)(W_ih + (size_t)R[j] * HDIM + kb) + c * 512));
                fma2(a0[j], wv.x, hv.x);
                fma2(a1[j], wv.y, hv.y);
            }
        }
        #pragma unroll
        for (int j = 0; j < 4; j++) {
            float2 u0 = unpack2(a0[j]), u1 = unpack2(a1[j]);
            xg[j] = (u0.x + u0.y) + (u1.x + u1.y);
        }
        #pragma unroll
        for (int off = 16; off; off >>= 1) {
            #pragma unroll
            for (int j = 0; j < 4; j++)
                xg[j] += __shfl_xor_sync(0xffffffffu, xg[j], off);
        }
        if (ch == 0) {
            #pragma unroll
            for (int j = 0; j < 4; j++)
                xg[j] += b_ih[R[j]] + b_hh[R[j]];
        }
    }

    float cstate = 0.f;   // cell state: warp 0 lanes 0..7

    // ---- step 0: h = 0 -> gates = x_gates ----
    if (l == 0) {
        #pragma unroll
        for (int j = 0; j < 4; j++) psum[w * 4 + j] = xg[j];
    }
    __syncthreads();
    if (w == 0) {
        float gv = psum[8 * (l >> 2) + (l & 3)] + psum[8 * (l >> 2) + (l & 3) + 4];
        const bool isG = (l >= 16) && (l < 24);
        float e = __expf(isG ? -2.0f * gv : -gv);
        float rr = __fdividef(1.0f, 1.0f + e);
        float v = isG ? fmaf(2.0f, rr, -1.0f) : rr;
        float fg = __shfl_sync(0xffffffffu, v, (l + 8)  & 31);
        float gg = __shfl_sync(0xffffffffu, v, (l + 16) & 31);
        float og = __shfl_sync(0xffffffffu, v, (l + 24) & 31);
        if (l < 8) {
            float c = fmaf(fg, cstate, v * gg);
            cstate  = c;
            float e2 = __expf(-2.0f * c);
            float h  = og * fmaf(2.0f, __fdividef(1.0f, 1.0f + e2), -1.0f);
            int col  = b * 8 + l;
            g_hbuf[1][col] = h;    // h_1 -> buf[1]
            out[col] = h;          // out row 0 = h_1
        }
        __syncwarp();
        if (l == 0) st_flag_release(&g_flags[b], 1u);
    }

    // ---- steps 1..N-1 ----
    for (int s = 1; s < N; s++) {
        // Warp 15 (SMSP 3; warp 0 is on SMSP 0) is the sole poller; all other
        // warps park at barrier A, issuing nothing.
        if (w == 15) {
            const unsigned tgt = (unsigned)s;
            for (;;) {
                unsigned f0 = ld_acquire_gpu(&g_flags[l]);
                unsigned f1 = ld_acquire_gpu(&g_flags[l + 32]);
                unsigned f2 = ld_acquire_gpu(&g_flags[l + 64]);
                unsigned f3 = ld_acquire_gpu(&g_flags[l + 96]);
                bool ok = (f0 >= tgt) & (f1 >= tgt) & (f2 >= tgt) & (f3 >= tgt);
                if (__all_sync(0xffffffffu, ok)) break;
            }
        }
        __syncthreads();   // (A) all flags seen; h_s globally published

        // Stage h_s: each warp loads its 64-float slice from L2 (.cg).
        {
            float2 hv = ldcg_f2((const float2*)&g_hbuf[s & 1][0] + (w * 32 + l));
            *(float2*)(hsm + w * 64 + 2 * l) = hv;
        }
        __syncthreads();   // (B) hsm ready (also fences psum reuse)

        // Matvec over this warp's column half: 4 rows, packed fp32x2 FMA.
        unsigned long long a0[4] = {0,0,0,0}, a1[4] = {0,0,0,0};
        #pragma unroll
        for (int c = 0; c < 4; c++) {
            ulonglong2 hv = *(const ulonglong2*)(hsm + kb + c * 128);
            #pragma unroll
            for (int j = 0; j < 4; j++) {
                fma2(a0[j], wt[j][c].x, hv.x);
                fma2(a1[j], wt[j][c].y, hv.y);
            }
        }
        float pv[4];
        #pragma unroll
        for (int j = 0; j < 4; j++) {
            float2 u0 = unpack2(a0[j]), u1 = unpack2(a1[j]);
            pv[j] = (u0.x + u0.y) + (u1.x + u1.y);
        }
        #pragma unroll
        for (int off = 16; off; off >>= 1) {
            #pragma unroll
            for (int j = 0; j < 4; j++)
                pv[j] += __shfl_xor_sync(0xffffffffu, pv[j], off);
        }
        if (l == 0) {
            #pragma unroll
            for (int j = 0; j < 4; j++) psum[w * 4 + j] = pv[j] + xg[j];
        }
        __syncthreads();   // (C) psums ready

        // Warp 0: combine pair partials, gates, state update, publish.
        if (w == 0) {
            float gv = psum[8 * (l >> 2) + (l & 3)] + psum[8 * (l >> 2) + (l & 3) + 4];
            const bool isG = (l >= 16) && (l < 24);
            float e = __expf(isG ? -2.0f * gv : -gv);
            float rr = __fdividef(1.0f, 1.0f + e);
            float v = isG ? fmaf(2.0f, rr, -1.0f) : rr;
            float fg = __shfl_sync(0xffffffffu, v, (l + 8)  & 31);
            float gg = __shfl_sync(0xffffffffu, v, (l + 16) & 31);
            float og = __shfl_sync(0xffffffffu, v, (l + 24) & 31);
            if (l < 8) {
                float c = fmaf(fg, cstate, v * gg);
                cstate  = c;
                float e2 = __expf(-2.0f * c);
                float h  = og * fmaf(2.0f, __fdividef(1.0f, 1.0f + e2), -1.0f);
                int col  = b * 8 + l;
                g_hbuf[(s + 1) & 1][col] = h;
                out[(size_t)s * HDIM + col] = h;   // out row s = h_{s+1}
            }
            __syncwarp();
            if (l == 0) st_flag_release(&g_flags[b], (unsigned)(s + 1));
        }
        // Warps 1..14 run straight to barrier A of step s+1 and park; only
        // warp 15 spins (on a different SMSP than warp 0). Barrier A of the
        // next iteration orders all hsm/psum reuse behind warp 0's reads.
    }
}

extern "C" void kernel_launch(void* const* d_in, const int* in_sizes, int n_in,
                              void* d_out, int out_size) {
    const float* x    = (const float*)d_in[0];   // projected_representation [1,1024]
    const float* Wih  = (const float*)d_in[1];   // [4096,1024]
    const float* Whh  = (const float*)d_in[2];   // [4096,1024]
    const float* bih  = (const float*)d_in[3];   // [4096]
    const float* bhh  = (const float*)d_in[4];   // [4096]
    const int*   nn   = (const int*)d_in[5];     // num_nodes
    float* out = (float*)d_out;                  // [N,1024] fp32

    lstm_init_kernel<<<1, NCTA>>>();
    lstm_kernel<<<NCTA, NTHR>>>(x, Wih, Whh, bih, bhh, nn, out);
}

// round 8
// speedup vs baseline: 5.5201x; 2.1062x over previous
#include <cuda_runtime.h>
#include <cstdint>

#define HDIM 1024
#define NCTA 128
#define NTHR 512

// Persistent cross-kernel state (allocation-free: __device__ globals).
__device__ unsigned g_counter;          // grid arrive counter (monotonic within a launch)
__device__ float g_hbuf[2][HDIM];       // double-buffered hidden state

__global__ void lstm_init_kernel() { g_counter = 0u; }

__device__ __forceinline__ unsigned ld_acquire_gpu(const unsigned* p) {
    unsigned v;
    asm volatile("ld.acquire.gpu.global.u32 %0, [%1];" : "=r"(v) : "l"(p) : "memory");
    return v;
}
__device__ __forceinline__ void red_release_gpu_add(unsigned* p, unsigned v) {
    asm volatile("red.release.gpu.global.add.u32 [%0], %1;" :: "l"(p), "r"(v) : "memory");
}
__device__ __forceinline__ float2 ldcg_f2(const float2* p) {
    float2 v;
    asm volatile("ld.global.cg.v2.f32 {%0,%1}, [%2];" : "=f"(v.x), "=f"(v.y) : "l"(p) : "memory");
    return v;
}
// Packed fp32x2 FMA (Blackwell): d.lo += a.lo*b.lo, d.hi += a.hi*b.hi (full fp32)
__device__ __forceinline__ void fma2(unsigned long long& d, unsigned long long a, unsigned long long b) {
    asm volatile("fma.rn.f32x2 %0, %1, %2, %0;" : "+l"(d) : "l"(a), "l"(b));
}
__device__ __forceinline__ float2 unpack2(unsigned long long v) {
    float2 r;
    asm("mov.b64 {%0, %1}, %2;" : "=f"(r.x), "=f"(r.y) : "l"(v));
    return r;
}

// 128 CTAs x 512 threads. CTA b owns hidden units [8b, 8b+8) => 32 gate rows
// (local row r = gate*8 + jj, global row R = (r>>3)*1024 + b*8 + (r&7)).
// Warp pair p = w>>1 owns local rows {4p..4p+3}; ch = w&1 selects the column
// half [512*ch, 512*ch+512). Each lane holds 4 rows x 16 cols of W_hh in
// registers (16 packed-f32x2 ulonglong2 = 64 floats). Partial row sums are
// combined across the warp pair through psum[] in shared memory.
// Sync: R3-proven scheme — single global counter, red.release arrive (one
// per CTA per step), tid==0 sole poller; all other warps park at barriers.
__global__ void __launch_bounds__(NTHR, 1)
lstm_kernel(const float* __restrict__ x,
            const float* __restrict__ W_ih,
            const float* __restrict__ W_hh,
            const float* __restrict__ b_ih,
            const float* __restrict__ b_hh,
            const int*   __restrict__ nn,
            float*       __restrict__ out)
{
    __shared__ float hsm[HDIM];
    __shared__ float psum[64];     // [warp*4 + rowslot]

    const int tid = threadIdx.x;
    const int w   = tid >> 5;
    const int l   = tid & 31;
    const int b   = blockIdx.x;
    const int N   = *nn;

    const int p   = w >> 1;
    const int ch  = w & 1;
    const int kb  = ch * 512 + l * 4;      // base column for this lane

    int R[4];
    #pragma unroll
    for (int j = 0; j < 4; j++) {
        int r = 4 * p + j;
        R[j] = (r >> 3) * HDIM + b * 8 + (r & 7);
    }

    // Stage x into hsm (reused for h each step).
    *(float2*)(hsm + 2 * tid) = *(const float2*)(x + 2 * tid);

    // Pin W_hh weights in registers: wt[j][c] covers row R[j], cols kb+c*128..+3.
    ulonglong2 wt[4][4];
    #pragma unroll
    for (int j = 0; j < 4; j++) {
        const char* base = (const char*)(W_hh + (size_t)R[j] * HDIM + kb);
        #pragma unroll
        for (int c = 0; c < 4; c++)
            wt[j][c] = __ldg((const ulonglong2*)(base + c * 512));
    }
    __syncthreads();   // x staged

    // x-gate partials over this warp's column half (+ biases on even warp only).
    float xg[4];
    {
        unsigned long long a0[4] = {0,0,0,0}, a1[4] = {0,0,0,0};
        #pragma unroll
        for (int c = 0; c < 4; c++) {
            ulonglong2 hv = *(const ulonglong2*)(hsm + kb + c * 128);
            #pragma unroll
            for (int j = 0; j < 4; j++) {
                ulonglong2 wv = __ldg((const ulonglong2*)
                    ((const char*)(W_ih + (size_t)R[j] * HDIM + kb) + c * 512));
                fma2(a0[j], wv.x, hv.x);
                fma2(a1[j], wv.y, hv.y);
            }
        }
        #pragma unroll
        for (int j = 0; j < 4; j++) {
            float2 u0 = unpack2(a0[j]), u1 = unpack2(a1[j]);
            xg[j] = (u0.x + u0.y) + (u1.x + u1.y);
        }
        #pragma unroll
        for (int off = 16; off; off >>= 1) {
            #pragma unroll
            for (int j = 0; j < 4; j++)
                xg[j] += __shfl_xor_sync(0xffffffffu, xg[j], off);
        }
        if (ch == 0) {
            #pragma unroll
            for (int j = 0; j < 4; j++)
                xg[j] += b_ih[R[j]] + b_hh[R[j]];
        }
    }

    float cstate = 0.f;   // cell state: warp 0 lanes 0..7

    // ---- step 0: h = 0 -> gates = x_gates ----
    if (l == 0) {
        #pragma unroll
        for (int j = 0; j < 4; j++) psum[w * 4 + j] = xg[j];
    }
    __syncthreads();
    if (w == 0) {
        float gv = psum[8 * (l >> 2) + (l & 3)] + psum[8 * (l >> 2) + (l & 3) + 4];
        const bool isG = (l >= 16) && (l < 24);
        float e = __expf(isG ? -2.0f * gv : -gv);
        float rr = __fdividef(1.0f, 1.0f + e);
        float v = isG ? fmaf(2.0f, rr, -1.0f) : rr;
        float fg = __shfl_sync(0xffffffffu, v, (l + 8)  & 31);
        float gg = __shfl_sync(0xffffffffu, v, (l + 16) & 31);
        float og = __shfl_sync(0xffffffffu, v, (l + 24) & 31);
        float h = 0.f;
        if (l < 8) {
            float c = fmaf(fg, cstate, v * gg);
            cstate  = c;
            float e2 = __expf(-2.0f * c);
            h = og * fmaf(2.0f, __fdividef(1.0f, 1.0f + e2), -1.0f);
            g_hbuf[1][b * 8 + l] = h;      // h_1 -> buf[1]
        }
        __syncwarp();
        if (l == 0) red_release_gpu_add(&g_counter, 1u);
        if (l < 8) out[b * 8 + l] = h;     // out row 0 = h_1 (off critical path)
    }

    // ---- steps 1..N-1 ----
    for (int s = 1; s < N; s++) {
        // tid 0 is the sole poller; all other threads park at barrier A.
        if (tid == 0) {
            const unsigned target = (unsigned)NCTA * (unsigned)s;
            while (ld_acquire_gpu(&g_counter) < target) { }
        }
        __syncthreads();   // (A) all 128 CTAs have published h_s

        // Stage h_s: each warp loads its 64-float slice from L2 (.cg).
        {
            float2 hv = ldcg_f2((const float2*)&g_hbuf[s & 1][0] + (w * 32 + l));
            *(float2*)(hsm + w * 64 + 2 * l) = hv;
        }
        __syncthreads();   // (B) hsm ready (also fences psum reuse)

        // Matvec over this warp's column half: 4 rows, packed fp32x2 FMA.
        unsigned long long a0[4] = {0,0,0,0}, a1[4] = {0,0,0,0};
        #pragma unroll
        for (int c = 0; c < 4; c++) {
            ulonglong2 hv = *(const ulonglong2*)(hsm + kb + c * 128);
            #pragma unroll
            for (int j = 0; j < 4; j++) {
                fma2(a0[j], wt[j][c].x, hv.x);
                fma2(a1[j], wt[j][c].y, hv.y);
            }
        }
        float pv[4];
        #pragma unroll
        for (int j = 0; j < 4; j++) {
            float2 u0 = unpack2(a0[j]), u1 = unpack2(a1[j]);
            pv[j] = (u0.x + u0.y) + (u1.x + u1.y);
        }
        #pragma unroll
        for (int off = 16; off; off >>= 1) {
            #pragma unroll
            for (int j = 0; j < 4; j++)
                pv[j] += __shfl_xor_sync(0xffffffffu, pv[j], off);
        }
        if (l == 0) {
            #pragma unroll
            for (int j = 0; j < 4; j++) psum[w * 4 + j] = pv[j] + xg[j];
        }
        __syncthreads();   // (C) psums ready

        // Warp 0: combine pair partials, gates, state update, publish.
        if (w == 0) {
            float gv = psum[8 * (l >> 2) + (l & 3)] + psum[8 * (l >> 2) + (l & 3) + 4];
            const bool isG = (l >= 16) && (l < 24);
            float e = __expf(isG ? -2.0f * gv : -gv);
            float rr = __fdividef(1.0f, 1.0f + e);
            float v = isG ? fmaf(2.0f, rr, -1.0f) : rr;
            float fg = __shfl_sync(0xffffffffu, v, (l + 8)  & 31);
            float gg = __shfl_sync(0xffffffffu, v, (l + 16) & 31);
            float og = __shfl_sync(0xffffffffu, v, (l + 24) & 31);
            float h = 0.f;
            if (l < 8) {
                float c = fmaf(fg, cstate, v * gg);
                cstate  = c;
                float e2 = __expf(-2.0f * c);
                h = og * fmaf(2.0f, __fdividef(1.0f, 1.0f + e2), -1.0f);
                g_hbuf[(s + 1) & 1][b * 8 + l] = h;    // publish FIRST
            }
            __syncwarp();
            if (l == 0) red_release_gpu_add(&g_counter, 1u);
            if (l < 8) out[(size_t)s * HDIM + b * 8 + l] = h;  // out row s = h_{s+1}
        }
        // Warps 1..15 run straight to barrier A of step s+1 and park; only
        // tid 0 polls. Barrier A of the next iteration orders all hsm/psum
        // reuse behind warp 0's reads (warp 0 arrives at A after its gates).
    }
}

extern "C" void kernel_launch(void* const* d_in, const int* in_sizes, int n_in,
                              void* d_out, int out_size) {
    const float* x    = (const float*)d_in[0];   // projected_representation [1,1024]
    const float* Wih  = (const float*)d_in[1];   // [4096,1024]
    const float* Whh  = (const float*)d_in[2];   // [4096,1024]
    const float* bih  = (const float*)d_in[3];   // [4096]
    const float* bhh  = (const float*)d_in[4];   // [4096]
    const int*   nn   = (const int*)d_in[5];     // num_nodes
    float* out = (float*)d_out;                  // [N,1024] fp32

    lstm_init_kernel<<<1, 1>>>();
    lstm_kernel<<<NCTA, NTHR>>>(x, Wih, Whh, bih, bhh, nn, out);
}